// round 10
// baseline (speedup 1.0000x reference)
#include <cuda_runtime.h>
#include <math.h>
#include <stdint.h>

#define DM   1024
#define NH   16
#define HD   64
#define BB   4
#define SS   2048
#define ROWS (BB*SS)   // 8192
#define CHUNK 64
#define NCH  (SS/CHUNK)       // 32 chunks per chain
#define NCI  (BB*NH*NCH)      // 2048 chunk instances
#define P65  65
#define SP   68               // pitch for split (hi/lo) smem arrays

#define WSZ  (DM*DM)
#define XSZ  (ROWS*DM)

// ---------------- scratch (static device buffers; no allocation) ------------
__device__ float g_q[XSZ];
__device__ float g_k[XSZ];
__device__ float g_v[XSZ];
__device__ float g_beta[ROWS*NH];
__device__ float g_attn[XSZ];

// pre-split tf32 operands
__device__ float g_xhi[XSZ];
__device__ float g_xlo[XSZ];
__device__ float g_yhi[XSZ];
__device__ float g_ylo[XSZ];
__device__ float g_whi[4*WSZ];   // Wq,Wk,Wv,Wo
__device__ float g_wlo[4*WSZ];

// chunked delta-rule scratch
__device__ float g_A [NCI*4096];
__device__ float g_KV[NCI*4096];
__device__ float g_U [NCI*4096];
__device__ float g_M0[NCI*4096];

__device__ float* g_ptrs[4];

__global__ void init_ptrs_k()
{
    g_ptrs[0] = g_q;
    g_ptrs[1] = g_k;
    g_ptrs[2] = g_v;
    g_ptrs[3] = g_attn;
}

__device__ __forceinline__ float sigmf(float x){ return 1.0f/(1.0f+__expf(-x)); }
__device__ __forceinline__ float siluf(float x){ return x * sigmf(x); }

__device__ __forceinline__ void zero44(float (&acc)[4][4])
{
    #pragma unroll
    for (int i = 0; i < 4; ++i)
        #pragma unroll
        for (int j = 0; j < 4; ++j)
            acc[i][j] = 0.f;
}

// ---------------- tf32 helpers ----------------------------------------------
__device__ __forceinline__ float f2tf32f(float x)
{
    uint32_t r;
    asm("cvt.rna.tf32.f32 %0, %1;" : "=r"(r) : "f"(x));
    return __uint_as_float(r);
}

__device__ __forceinline__ void mma_tf32(float (&d)[4],
    float a0, float a1, float a2, float a3, float b0, float b1)
{
    asm volatile(
        "mma.sync.aligned.m16n8k8.row.col.f32.tf32.tf32.f32 "
        "{%0,%1,%2,%3}, {%4,%5,%6,%7}, {%8,%9}, {%0,%1,%2,%3};"
        : "+f"(d[0]), "+f"(d[1]), "+f"(d[2]), "+f"(d[3])
        : "r"(__float_as_uint(a0)), "r"(__float_as_uint(a1)),
          "r"(__float_as_uint(a2)), "r"(__float_as_uint(a3)),
          "r"(__float_as_uint(b0)), "r"(__float_as_uint(b1)));
}

__device__ __forceinline__ void cp16(uint32_t dst_smem, const void* src)
{
    asm volatile("cp.async.ca.shared.global [%0], [%1], 16;"
                 :: "r"(dst_smem), "l"(src));
}
__device__ __forceinline__ void cp_commit()
{
    asm volatile("cp.async.commit_group;");
}
template<int N> __device__ __forceinline__ void cp_wait()
{
    asm volatile("cp.async.wait_group %0;" :: "n"(N));
}

// ---------------- split x = hi + lo (tf32 each) ------------------------------
__global__ __launch_bounds__(256) void split5_k(
    const float* __restrict__ x,
    const float* __restrict__ Wq, const float* __restrict__ Wk,
    const float* __restrict__ Wv, const float* __restrict__ Wo)
{
    const int z = blockIdx.z;
    const float* src; float* hi; float* lo; size_t n;
    if (z == 0)      { src = x;  hi = g_xhi;         lo = g_xlo;         n = XSZ; }
    else if (z == 1) { src = Wq; hi = g_whi;         lo = g_wlo;         n = WSZ; }
    else if (z == 2) { src = Wk; hi = g_whi + WSZ;   lo = g_wlo + WSZ;   n = WSZ; }
    else if (z == 3) { src = Wv; hi = g_whi + 2*WSZ; lo = g_wlo + 2*WSZ; n = WSZ; }
    else             { src = Wo; hi = g_whi + 3*WSZ; lo = g_wlo + 3*WSZ; n = WSZ; }

    size_t i4 = (size_t)blockIdx.x * 256 + threadIdx.x;
    if (i4 * 4 >= n) return;
    float4 v = ((const float4*)src)[i4];
    float4 h, l;
    h.x = f2tf32f(v.x); l.x = f2tf32f(v.x - h.x);
    h.y = f2tf32f(v.y); l.y = f2tf32f(v.y - h.y);
    h.z = f2tf32f(v.z); l.z = f2tf32f(v.z - h.z);
    h.w = f2tf32f(v.w); l.w = f2tf32f(v.w - h.w);
    ((float4*)hi)[i4] = h;
    ((float4*)lo)[i4] = l;
}

// ---------------- 3xTF32 GEMM v2: pre-split operands, cp.async 2-stage -------
#define GP   20
#define GBUF (128*GP)
#define OFF_AH 0
#define OFF_AL (2*GBUF)
#define OFF_WH (4*GBUF)
#define OFF_WL (6*GBUF)
#define GSMEM  (8*GBUF*4)

template<int ACT>
__device__ __forceinline__ void gemm3t_v2(
    const float* __restrict__ Ahi, const float* __restrict__ Alo,
    const float* __restrict__ Whi, const float* __restrict__ Wlo,
    float* __restrict__ C, int M, int N, int K)
{
    extern __shared__ float sm[];
    const uint32_t sbase = (uint32_t)__cvta_generic_to_shared(sm);

    const int tid  = threadIdx.x;
    const int lane = tid & 31;
    const int wid  = tid >> 5;
    const int m0   = blockIdx.y * 128;
    const int n0   = blockIdx.x * 128;
    const int m0w  = (wid >> 1) * 32;
    const int n0w  = (wid & 1)  * 64;
    const int rr   = lane >> 2;
    const int qq   = lane & 3;

    float acc[2][8][4];
    #pragma unroll
    for (int i = 0; i < 2; ++i)
        #pragma unroll
        for (int j = 0; j < 8; ++j)
            #pragma unroll
            for (int r = 0; r < 4; ++r) acc[i][j][r] = 0.f;

    auto issue = [&](int b, int kt) {
        const int k0 = kt * 16;
        #pragma unroll
        for (int cc = 0; cc < 2; ++cc) {
            const int c   = tid + cc * 256;
            const int row = c >> 2;
            const int q4  = (c & 3) * 4;
            const uint32_t soff = (uint32_t)((b*GBUF + row*GP + q4) * 4);
            const size_t ga = (size_t)(m0 + row) * K + k0 + q4;
            const size_t gw = (size_t)(n0 + row) * K + k0 + q4;
            cp16(sbase + OFF_AH*4 + soff, Ahi + ga);
            cp16(sbase + OFF_AL*4 + soff, Alo + ga);
            cp16(sbase + OFF_WH*4 + soff, Whi + gw);
            cp16(sbase + OFF_WL*4 + soff, Wlo + gw);
        }
    };

    const int NT = K / 16;
    issue(0, 0);
    cp_commit();

    for (int kt = 0; kt < NT; ++kt) {
        const int cur = kt & 1;
        if (kt + 1 < NT) {
            issue(cur ^ 1, kt + 1);
            cp_commit();
            cp_wait<1>();
        } else {
            cp_wait<0>();
        }
        __syncthreads();

        const float* sAh = sm + OFF_AH + cur*GBUF;
        const float* sAl = sm + OFF_AL + cur*GBUF;
        const float* sWh = sm + OFF_WH + cur*GBUF;
        const float* sWl = sm + OFF_WL + cur*GBUF;

        #pragma unroll
        for (int c = 0; c < 2; ++c) {
            const int kc = c * 8;
            float ah[2][4], al[2][4];
            #pragma unroll
            for (int i = 0; i < 2; ++i) {
                const int mb = m0w + i * 16;
                ah[i][0] = sAh[(mb+rr  )*GP + kc+qq  ];
                ah[i][1] = sAh[(mb+rr+8)*GP + kc+qq  ];
                ah[i][2] = sAh[(mb+rr  )*GP + kc+qq+4];
                ah[i][3] = sAh[(mb+rr+8)*GP + kc+qq+4];
                al[i][0] = sAl[(mb+rr  )*GP + kc+qq  ];
                al[i][1] = sAl[(mb+rr+8)*GP + kc+qq  ];
                al[i][2] = sAl[(mb+rr  )*GP + kc+qq+4];
                al[i][3] = sAl[(mb+rr+8)*GP + kc+qq+4];
            }
            #pragma unroll
            for (int j = 0; j < 8; ++j) {
                const int nb = n0w + j * 8 + rr;
                float bh0 = sWh[nb*GP + kc+qq  ];
                float bh1 = sWh[nb*GP + kc+qq+4];
                float bl0 = sWl[nb*GP + kc+qq  ];
                float bl1 = sWl[nb*GP + kc+qq+4];
                #pragma unroll
                for (int i = 0; i < 2; ++i) {
                    mma_tf32(acc[i][j], ah[i][0], ah[i][1], ah[i][2], ah[i][3], bh0, bh1);
                    mma_tf32(acc[i][j], ah[i][0], ah[i][1], ah[i][2], ah[i][3], bl0, bl1);
                    mma_tf32(acc[i][j], al[i][0], al[i][1], al[i][2], al[i][3], bh0, bh1);
                }
            }
        }
        __syncthreads();
    }

    #pragma unroll
    for (int i = 0; i < 2; ++i) {
        #pragma unroll
        for (int j = 0; j < 8; ++j) {
            const int row0 = m0 + m0w + i * 16 + rr;
            const int col  = n0 + n0w + j * 8 + qq * 2;
            float2 v0, v1;
            v0.x = acc[i][j][0]; v0.y = acc[i][j][1];
            v1.x = acc[i][j][2]; v1.y = acc[i][j][3];
            if (ACT == 1) {
                v0.x = siluf(v0.x); v0.y = siluf(v0.y);
                v1.x = siluf(v1.x); v1.y = siluf(v1.y);
            }
            *(float2*)&C[(size_t)row0       * N + col] = v0;
            *(float2*)&C[(size_t)(row0 + 8) * N + col] = v1;
        }
    }
}

__global__ __launch_bounds__(256, 2) void gemm_qkv(int M, int N, int K)
{
    const int z = blockIdx.z;
    gemm3t_v2<1>(g_xhi, g_xlo, g_whi + (size_t)z*WSZ, g_wlo + (size_t)z*WSZ,
                 g_ptrs[z], M, N, K);
}

__global__ __launch_bounds__(256, 2) void gemm_out(float* __restrict__ C,
                                                   int M, int N, int K)
{
    gemm3t_v2<0>(g_yhi, g_ylo, g_whi + 3*(size_t)WSZ, g_wlo + 3*(size_t)WSZ,
                 C, M, N, K);
}

// ---------------- beta = sigmoid(x @ Wbeta^T) --------------------------------
__global__ __launch_bounds__(128) void beta_gemv(
    const float* __restrict__ x, const float* __restrict__ Wb)
{
    const int row = blockIdx.x;
    __shared__ float xs[DM];
    const float4* xr = (const float4*)(x + (size_t)row * DM);
    float4* xs4 = (float4*)xs;
    xs4[threadIdx.x]       = xr[threadIdx.x];
    xs4[threadIdx.x + 128] = xr[threadIdx.x + 128];
    __syncthreads();

    const int j  = threadIdx.x >> 3;
    const int l8 = threadIdx.x & 7;
    const float* wr = Wb + (size_t)j * DM;
    float s = 0.f;
    for (int i = 0; i < DM/8; ++i) {
        int k = l8 + i*8;
        s += xs[k] * wr[k];
    }
    #pragma unroll
    for (int off = 4; off > 0; off >>= 1)
        s += __shfl_down_sync(0xffffffffu, s, off, 8);
    if (l8 == 0) g_beta[(size_t)row * NH + j] = sigmf(s);
}

// ---------------- per-head l2 normalize (in place) ---------------------------
__global__ __launch_bounds__(512) void l2norm_k()
{
    float* p = g_ptrs[blockIdx.y];   // 0 -> g_q, 1 -> g_k
    const int row  = blockIdx.x;
    const int w    = threadIdx.x >> 5;
    const int lane = threadIdx.x & 31;
    const size_t base = (size_t)row * DM + w * HD;
    float a = p[base + lane];
    float b = p[base + 32 + lane];
    float ss = a*a + b*b;
    #pragma unroll
    for (int off = 16; off > 0; off >>= 1)
        ss += __shfl_xor_sync(0xffffffffu, ss, off);
    float sc = 1.0f / (sqrtf(ss) + 1e-6f);
    p[base + lane]      = a * sc;
    p[base + 32 + lane] = b * sc;
}

// ---------------- small 64x64x64 smem FFMA micro-kernels (parallel kernels) --
__device__ __forceinline__ void gemm_rr(
    const float* __restrict__ A, const float* __restrict__ B,
    float (&acc)[4][4], int i0, int j0)
{
    #pragma unroll 4
    for (int x = 0; x < 64; ++x) {
        float a0 = A[(i0+0)*P65+x], a1 = A[(i0+1)*P65+x];
        float a2 = A[(i0+2)*P65+x], a3 = A[(i0+3)*P65+x];
        float b0 = B[(j0+0)*P65+x], b1 = B[(j0+1)*P65+x];
        float b2 = B[(j0+2)*P65+x], b3 = B[(j0+3)*P65+x];
        acc[0][0]+=a0*b0; acc[0][1]+=a0*b1; acc[0][2]+=a0*b2; acc[0][3]+=a0*b3;
        acc[1][0]+=a1*b0; acc[1][1]+=a1*b1; acc[1][2]+=a1*b2; acc[1][3]+=a1*b3;
        acc[2][0]+=a2*b0; acc[2][1]+=a2*b1; acc[2][2]+=a2*b2; acc[2][3]+=a2*b3;
        acc[3][0]+=a3*b0; acc[3][1]+=a3*b1; acc[3][2]+=a3*b2; acc[3][3]+=a3*b3;
    }
}

__device__ __forceinline__ void gemm_rc(
    const float* __restrict__ A, const float* __restrict__ B,
    float (&acc)[4][4], int i0, int j0)
{
    #pragma unroll 4
    for (int x = 0; x < 64; ++x) {
        float a0 = A[(i0+0)*P65+x], a1 = A[(i0+1)*P65+x];
        float a2 = A[(i0+2)*P65+x], a3 = A[(i0+3)*P65+x];
        float b0 = B[x*P65+j0+0], b1 = B[x*P65+j0+1];
        float b2 = B[x*P65+j0+2], b3 = B[x*P65+j0+3];
        acc[0][0]+=a0*b0; acc[0][1]+=a0*b1; acc[0][2]+=a0*b2; acc[0][3]+=a0*b3;
        acc[1][0]+=a1*b0; acc[1][1]+=a1*b1; acc[1][2]+=a1*b2; acc[1][3]+=a1*b3;
        acc[2][0]+=a2*b0; acc[2][1]+=a2*b1; acc[2][2]+=a2*b2; acc[2][3]+=a2*b3;
        acc[3][0]+=a3*b0; acc[3][1]+=a3*b1; acc[3][2]+=a3*b2; acc[3][3]+=a3*b3;
    }
}

// ---------------- chunk pre-kernel: A = K K^T, KV = K V^T --------------------
__global__ __launch_bounds__(256) void chunk_pre_k()
{
    __shared__ float sK[64*P65];
    __shared__ float sV[64*P65];

    const int ci    = blockIdx.x;
    const int chain = ci >> 5;
    const int c     = ci & 31;
    const int b     = chain >> 4;
    const int n     = chain & 15;
    const int tid   = threadIdx.x;
    const int i0    = (tid >> 4) << 2;
    const int j0    = (tid & 15) << 2;
    const size_t rbase = (size_t)(b*SS + c*CHUNK);

    for (int idx = tid; idx < 4096; idx += 256) {
        int t = idx >> 6, h = idx & 63;
        size_t g = (rbase + t) * DM + n*HD + h;
        sK[t*P65+h] = g_k[g];
        sV[t*P65+h] = g_v[g];
    }
    __syncthreads();

    float acc[4][4];
    zero44(acc);
    gemm_rr(sK, sK, acc, i0, j0);
    #pragma unroll
    for (int i = 0; i < 4; ++i)
        #pragma unroll
        for (int j = 0; j < 4; ++j)
            g_A[(size_t)ci*4096 + (i0+i)*64 + j0+j] = acc[i][j];

    zero44(acc);
    gemm_rr(sK, sV, acc, i0, j0);
    #pragma unroll
    for (int i = 0; i < 4; ++i)
        #pragma unroll
        for (int j = 0; j < 4; ++j)
            g_KV[(size_t)ci*4096 + (i0+i)*64 + j0+j] = acc[i][j];
}

// ---------------- 64x64x64 3xTF32 mma for the serial core --------------------
template<int AT, int BT>
__device__ __forceinline__ void mma64(
    const float* __restrict__ Ah, const float* __restrict__ Al,
    const float* __restrict__ Bh, const float* __restrict__ Bl,
    float (&acc)[4][4], int m0, int nb0, int rr, int qq)
{
    #pragma unroll
    for (int ks = 0; ks < 8; ++ks) {
        const int kk = ks * 8;
        float ah0,ah1,ah2,ah3, al0,al1,al2,al3;
        if (AT == 0) {
            ah0 = Ah[(m0+rr  )*SP + kk+qq  ]; ah1 = Ah[(m0+rr+8)*SP + kk+qq  ];
            ah2 = Ah[(m0+rr  )*SP + kk+qq+4]; ah3 = Ah[(m0+rr+8)*SP + kk+qq+4];
            al0 = Al[(m0+rr  )*SP + kk+qq  ]; al1 = Al[(m0+rr+8)*SP + kk+qq  ];
            al2 = Al[(m0+rr  )*SP + kk+qq+4]; al3 = Al[(m0+rr+8)*SP + kk+qq+4];
        } else {
            ah0 = Ah[(kk+qq  )*SP + m0+rr  ]; ah1 = Ah[(kk+qq  )*SP + m0+rr+8];
            ah2 = Ah[(kk+qq+4)*SP + m0+rr  ]; ah3 = Ah[(kk+qq+4)*SP + m0+rr+8];
            al0 = Al[(kk+qq  )*SP + m0+rr  ]; al1 = Al[(kk+qq  )*SP + m0+rr+8];
            al2 = Al[(kk+qq+4)*SP + m0+rr  ]; al3 = Al[(kk+qq+4)*SP + m0+rr+8];
        }
        #pragma unroll
        for (int j = 0; j < 4; ++j) {
            const int nn = nb0 + j * 8;
            float bh0, bh1, bl0, bl1;
            if (BT == 0) {
                bh0 = Bh[(nn+rr)*SP + kk+qq]; bh1 = Bh[(nn+rr)*SP + kk+qq+4];
                bl0 = Bl[(nn+rr)*SP + kk+qq]; bl1 = Bl[(nn+rr)*SP + kk+qq+4];
            } else {
                bh0 = Bh[(kk+qq)*SP + nn+rr]; bh1 = Bh[(kk+qq+4)*SP + nn+rr];
                bl0 = Bl[(kk+qq)*SP + nn+rr]; bl1 = Bl[(kk+qq+4)*SP + nn+rr];
            }
            mma_tf32(acc[j], ah0, ah1, ah2, ah3, bh0, bh1);
            mma_tf32(acc[j], ah0, ah1, ah2, ah3, bl0, bl1);
            mma_tf32(acc[j], al0, al1, al2, al3, bh0, bh1);
        }
    }
}

// ---------------- serial core v2: tensor gemms + register-D solve ------------
#define CORE_SMEM ((3*64*P65 + 10*64*SP + 64) * 4)

__global__ __launch_bounds__(256) void delta_core_k()
{
    extern __shared__ float smc[];
    float* sV  = smc;
    float* sR  = sV  + 64*P65;
    float* sA  = sR  + 64*P65;
    float* sKh = sA  + 64*P65;
    float* sKl = sKh + 64*SP;
    float* sMh = sKl + 64*SP;
    float* sMl = sMh + 64*SP;
    float* sTh = sMl + 64*SP;
    float* sTl = sTh + 64*SP;
    float* sGh = sTl + 64*SP;
    float* sGl = sGh + 64*SP;
    float* sUh = sGl + 64*SP;
    float* sUl = sUh + 64*SP;
    float* sb  = sUl + 64*SP;

    const int chain = blockIdx.x;
    const int b     = chain >> 4;
    const int n     = chain & 15;
    const int tid   = threadIdx.x;
    const int lane  = tid & 31;
    const int wid   = tid >> 5;
    const int m0    = (wid >> 1) * 16;
    const int nb0   = (wid & 1)  * 32;
    const int rr    = lane >> 2;
    const int qq    = lane & 3;
    const int tb    = tid >> 4;    // solve: G-rows 4tb..4tb+3
    const int vb    = tid & 15;    // solve: t'-cols 4vb..4vb+3

    for (int idx = tid; idx < 64*SP; idx += 256) { sMh[idx] = 0.f; sMl[idx] = 0.f; }
    __syncthreads();

    for (int c = 0; c < NCH; ++c) {
        const int ci = chain * NCH + c;
        const size_t rbase = (size_t)(b*SS + c*CHUNK);

        // ---- loads, checkpoint, zero G ----
        for (int idx = tid; idx < 4096; idx += 256) {
            int t = idx >> 6, h = idx & 63;
            size_t g = (rbase + t) * DM + n*HD + h;
            float kv = g_k[g];
            float kh = f2tf32f(kv);
            sKh[t*SP+h] = kh;
            sKl[t*SP+h] = f2tf32f(kv - kh);
            sV[t*P65+h] = g_v[g];
            sA[t*P65+h] = g_A [(size_t)ci*4096 + idx];
            sR[t*P65+h] = g_KV[(size_t)ci*4096 + idx];
            g_M0[(size_t)ci*4096 + idx] = sMh[t*SP+h] + sMl[t*SP+h];
        }
        for (int idx = tid; idx < 64*SP; idx += 256) { sGh[idx] = 0.f; sGl[idx] = 0.f; }
        if (tid < 64) sb[tid] = g_beta[(rbase + tid)*NH + n];
        __syncthreads();

        // ---- g1: T1[t,j] = sum_x K[t,x] M[j,x]  -> split T1 ----
        {
            float acc[4][4];
            zero44(acc);
            mma64<0,0>(sKh, sKl, sMh, sMl, acc, m0, nb0, rr, qq);
            #pragma unroll
            for (int j = 0; j < 4; ++j) {
                const int col = nb0 + j*8 + 2*qq;
                float v0 = acc[j][0], v1 = acc[j][1], v2 = acc[j][2], v3 = acc[j][3];
                float h0 = f2tf32f(v0), h1 = f2tf32f(v1), h2 = f2tf32f(v2), h3 = f2tf32f(v3);
                sTh[(m0+rr  )*SP + col  ] = h0; sTl[(m0+rr  )*SP + col  ] = f2tf32f(v0 - h0);
                sTh[(m0+rr  )*SP + col+1] = h1; sTl[(m0+rr  )*SP + col+1] = f2tf32f(v1 - h1);
                sTh[(m0+rr+8)*SP + col  ] = h2; sTl[(m0+rr+8)*SP + col  ] = f2tf32f(v2 - h2);
                sTh[(m0+rr+8)*SP + col+1] = h3; sTl[(m0+rr+8)*SP + col+1] = f2tf32f(v3 - h3);
            }
        }
        __syncthreads();

        // ---- g2: P[t',t] = sum_h K[t',h] T1[t,h];  R = KV - P ----
        {
            float acc[4][4];
            zero44(acc);
            mma64<0,0>(sKh, sKl, sTh, sTl, acc, m0, nb0, rr, qq);
            #pragma unroll
            for (int j = 0; j < 4; ++j) {
                const int col = nb0 + j*8 + 2*qq;
                sR[(m0+rr  )*P65 + col  ] -= acc[j][0];
                sR[(m0+rr  )*P65 + col+1] -= acc[j][1];
                sR[(m0+rr+8)*P65 + col  ] -= acc[j][2];
                sR[(m0+rr+8)*P65 + col+1] -= acc[j][3];
            }
        }
        __syncthreads();

        // ---- solve: G[t',t] = b_t (R[t',t] - sum_{r<t} G[t,r] A[t',r]) ----
        // D[i][j] (regs) = sum_r G[4tb+i, r] * A[4vb+j, r]
        {
            float D[4][4];
            zero44(D);
            for (int t = 0; t < 64; ++t) {
                if (tb == (t >> 2)) {              // row owner: rows 4tb..4tb+3
                    const int i = t & 3;
                    #pragma unroll
                    for (int j = 0; j < 4; ++j) {
                        const int tp = 4*vb + j;
                        if (tp > t) {
                            float val = sb[t] * (sR[tp*P65 + t] - D[i][j]);
                            float gh = f2tf32f(val);
                            sGh[tp*SP + t] = gh;
                            sGl[tp*SP + t] = f2tf32f(val - gh);
                        }
                    }
                }
                __syncthreads();
                float ga[4], aa[4];
                #pragma unroll
                for (int i = 0; i < 4; ++i)
                    ga[i] = sGh[(4*tb+i)*SP + t] + sGl[(4*tb+i)*SP + t];
                #pragma unroll
                for (int j = 0; j < 4; ++j)
                    aa[j] = sA[(4*vb+j)*P65 + t];
                #pragma unroll
                for (int i = 0; i < 4; ++i)
                    #pragma unroll
                    for (int j = 0; j < 4; ++j)
                        D[i][j] += ga[i] * aa[j];
            }
        }
        __syncthreads();

        // ---- g3: GK[t,d] = sum_r G[t,r] K[r,d];  U = b(V - T1 - GK) ----
        {
            float acc[4][4];
            zero44(acc);
            mma64<0,1>(sGh, sGl, sKh, sKl, acc, m0, nb0, rr, qq);
            const float b0 = sb[m0+rr], b1 = sb[m0+rr+8];
            #pragma unroll
            for (int j = 0; j < 4; ++j) {
                const int col = nb0 + j*8 + 2*qq;
                #pragma unroll
                for (int s = 0; s < 2; ++s) {
                    const int row = (s == 0) ? (m0+rr) : (m0+rr+8);
                    const float bb = (s == 0) ? b0 : b1;
                    #pragma unroll
                    for (int e = 0; e < 2; ++e) {
                        const int d = col + e;
                        const float gk = acc[j][s*2 + e];
                        const float t1 = sTh[row*SP + d] + sTl[row*SP + d];
                        const float u  = bb * (sV[row*P65 + d] - t1 - gk);
                        g_U[(size_t)ci*4096 + row*64 + d] = u;
                        float uh = f2tf32f(u);
                        sUh[row*SP + d] = uh;
                        sUl[row*SP + d] = f2tf32f(u - uh);
                    }
                }
            }
        }
        __syncthreads();

        // ---- g4: dM[h,d] = sum_t K[t,h] U[t,d];  M += dM (resplit) ----
        {
            float acc[4][4];
            zero44(acc);
            mma64<1,1>(sKh, sKl, sUh, sUl, acc, m0, nb0, rr, qq);
            #pragma unroll
            for (int j = 0; j < 4; ++j) {
                const int col = nb0 + j*8 + 2*qq;
                #pragma unroll
                for (int s = 0; s < 2; ++s) {
                    const int row = (s == 0) ? (m0+rr) : (m0+rr+8);
                    #pragma unroll
                    for (int e = 0; e < 2; ++e) {
                        const int d = col + e;
                        float mval = sMh[row*SP + d] + sMl[row*SP + d] + acc[j][s*2 + e];
                        float mh = f2tf32f(mval);
                        sMh[row*SP + d] = mh;
                        sMl[row*SP + d] = f2tf32f(mval - mh);
                    }
                }
            }
        }
        __syncthreads();
    }
}

// ---------------- epilogue: Out = Q M0 + tril(QK^T,-1) U  --------------------
__global__ __launch_bounds__(256) void delta_out_k()
{
    extern __shared__ float smo[];
    float* sQ  = smo;
    float* sKQ = sQ  + 64*P65;
    float* sM0 = sKQ + 64*P65;
    float* sU  = sM0 + 64*P65;

    const int ci    = blockIdx.x;
    const int chain = ci >> 5;
    const int c     = ci & 31;
    const int b     = chain >> 4;
    const int n     = chain & 15;
    const int tid   = threadIdx.x;
    const int i0    = (tid >> 4) << 2;
    const int j0    = (tid & 15) << 2;
    const size_t rbase = (size_t)(b*SS + c*CHUNK);

    for (int idx = tid; idx < 4096; idx += 256) {
        int t = idx >> 6, h = idx & 63;
        size_t g = (rbase + t) * DM + n*HD + h;
        sQ [t*P65+h] = g_q[g];
        sKQ[t*P65+h] = g_k[g];
        sM0[t*P65+h] = g_M0[(size_t)ci*4096 + idx];
        sU [t*P65+h] = g_U [(size_t)ci*4096 + idx];
    }
    __syncthreads();

    float acc[4][4];
    zero44(acc);
    gemm_rr(sQ, sKQ, acc, i0, j0);
    __syncthreads();
    #pragma unroll
    for (int i = 0; i < 4; ++i)
        #pragma unroll
        for (int j = 0; j < 4; ++j)
            sKQ[(i0+i)*P65 + j0+j] = (i0+i) > (j0+j) ? acc[i][j] : 0.f;
    __syncthreads();

    zero44(acc);
    gemm_rc(sQ,  sM0, acc, i0, j0);
    gemm_rc(sKQ, sU,  acc, i0, j0);

    #pragma unroll
    for (int i = 0; i < 4; ++i)
        #pragma unroll
        for (int j = 0; j < 4; ++j)
            g_attn[(rbase + i0+i)*DM + n*HD + j0+j] = acc[i][j];
}

// ---------------- RMSNorm (fused tf32 split of y) ----------------------------
__global__ __launch_bounds__(256) void rmsnorm_k(const float* __restrict__ w)
{
    const float* x = g_attn;
    const int row = blockIdx.x;
    const float4* xr = (const float4*)(x + (size_t)row * DM);
    float4 xv = xr[threadIdx.x];
    float ss = xv.x*xv.x + xv.y*xv.y + xv.z*xv.z + xv.w*xv.w;

    __shared__ float red[8];
    #pragma unroll
    for (int off = 16; off > 0; off >>= 1)
        ss += __shfl_xor_sync(0xffffffffu, ss, off);
    if ((threadIdx.x & 31) == 0) red[threadIdx.x >> 5] = ss;
    __syncthreads();
    float total = 0.f;
    #pragma unroll
    for (int i = 0; i < 8; ++i) total += red[i];

    const float inv = rsqrtf(total * (1.0f/DM) + 1e-6f);
    const float4* wr = (const float4*)w;
    float4 wv = wr[threadIdx.x];
    float4 o, h, l;
    o.x = xv.x * inv * wv.x; h.x = f2tf32f(o.x); l.x = f2tf32f(o.x - h.x);
    o.y = xv.y * inv * wv.y; h.y = f2tf32f(o.y); l.y = f2tf32f(o.y - h.y);
    o.z = xv.z * inv * wv.z; h.z = f2tf32f(o.z); l.z = f2tf32f(o.z - h.z);
    o.w = xv.w * inv * wv.w; h.w = f2tf32f(o.w); l.w = f2tf32f(o.w - h.w);
    ((float4*)(g_yhi + (size_t)row * DM))[threadIdx.x] = h;
    ((float4*)(g_ylo + (size_t)row * DM))[threadIdx.x] = l;
}

// ---------------- launcher ---------------------------------------------------
extern "C" void kernel_launch(void* const* d_in, const int* in_sizes, int n_in,
                              void* d_out, int out_size)
{
    const float* x   = (const float*)d_in[0];
    const float* Wq  = (const float*)d_in[1];
    const float* Wk  = (const float*)d_in[2];
    const float* Wv  = (const float*)d_in[3];
    const float* Wo  = (const float*)d_in[4];
    const float* Wb  = (const float*)d_in[5];
    const float* rw  = (const float*)d_in[6];
    float* out = (float*)d_out;

    const int epi_smem  = (4*64*P65) * 4;
    cudaFuncSetAttribute(delta_core_k, cudaFuncAttributeMaxDynamicSharedMemorySize, CORE_SMEM);
    cudaFuncSetAttribute(delta_out_k,  cudaFuncAttributeMaxDynamicSharedMemorySize, epi_smem);
    cudaFuncSetAttribute(gemm_qkv, cudaFuncAttributeMaxDynamicSharedMemorySize, GSMEM);
    cudaFuncSetAttribute(gemm_out, cudaFuncAttributeMaxDynamicSharedMemorySize, GSMEM);

    init_ptrs_k<<<1, 1>>>();

    dim3 gsplit(XSZ/4/256, 1, 5);
    split5_k<<<gsplit, 256>>>(x, Wq, Wk, Wv, Wo);

    beta_gemv<<<ROWS, 128>>>(x, Wb);

    dim3 gqkv(DM/128, ROWS/128, 3);
    gemm_qkv<<<gqkv, 256, GSMEM>>>(ROWS, DM, DM);

    dim3 gnorm(ROWS, 2);
    l2norm_k<<<gnorm, 512>>>();

    chunk_pre_k<<<NCI, 256>>>();
    delta_core_k<<<BB*NH, 256, CORE_SMEM>>>();
    delta_out_k<<<NCI, 256, epi_smem>>>();

    rmsnorm_k<<<ROWS, 256>>>(rw);

    dim3 go(DM/128, ROWS/128);
    gemm_out<<<go, 256, GSMEM>>>(out, ROWS, DM, DM);
}

// round 11
// speedup vs baseline: 1.3075x; 1.3075x over previous
#include <cuda_runtime.h>
#include <cuda_bf16.h>
#include <math.h>
#include <stdint.h>

#define DM   1024
#define NH   16
#define HD   64
#define BB   4
#define SS   2048
#define ROWS (BB*SS)   // 8192
#define CHUNK 64
#define NCH  (SS/CHUNK)       // 32 chunks per chain
#define NCI  (BB*NH*NCH)      // 2048 chunk instances
#define P65  65

#define WSZ  (DM*DM)
#define XSZ  (ROWS*DM)

// ---------------- scratch (static device buffers; no allocation) ------------
__device__ float g_q[XSZ];
__device__ float g_k[XSZ];
__device__ float g_v[XSZ];
__device__ float g_beta[ROWS*NH];
__device__ float g_attn[XSZ];

// pre-split bf16 operands (x = hi + lo, both bf16)
__device__ __nv_bfloat16 g_xhi[XSZ];
__device__ __nv_bfloat16 g_xlo[XSZ];
__device__ __nv_bfloat16 g_yhi[XSZ];
__device__ __nv_bfloat16 g_ylo[XSZ];
__device__ __nv_bfloat16 g_whi[4*WSZ];   // Wq,Wk,Wv,Wo
__device__ __nv_bfloat16 g_wlo[4*WSZ];

// chunked delta-rule scratch
__device__ float g_A [NCI*4096];
__device__ float g_KV[NCI*4096];
__device__ float g_U [NCI*4096];
__device__ float g_M0[NCI*4096];

__device__ float* g_ptrs[4];

__global__ void init_ptrs_k()
{
    g_ptrs[0] = g_q;
    g_ptrs[1] = g_k;
    g_ptrs[2] = g_v;
    g_ptrs[3] = g_attn;
}

__device__ __forceinline__ float sigmf(float x){ return 1.0f/(1.0f+__expf(-x)); }
__device__ __forceinline__ float siluf(float x){ return x * sigmf(x); }

__device__ __forceinline__ void zero44(float (&acc)[4][4])
{
    #pragma unroll
    for (int i = 0; i < 4; ++i)
        #pragma unroll
        for (int j = 0; j < 4; ++j)
            acc[i][j] = 0.f;
}

// ---------------- bf16 split helpers -----------------------------------------
__device__ __forceinline__ __nv_bfloat162 split_hi2(float a, float b,
                                                    float& ra, float& rb)
{
    __nv_bfloat16 ha = __float2bfloat16(a);
    __nv_bfloat16 hb = __float2bfloat16(b);
    ra = a - __bfloat162float(ha);
    rb = b - __bfloat162float(hb);
    __nv_bfloat162 p; p.x = ha; p.y = hb; return p;
}

// ---------------- mma m16n8k16 bf16 ------------------------------------------
__device__ __forceinline__ void mma_bf16(float (&d)[4],
    uint32_t a0, uint32_t a1, uint32_t a2, uint32_t a3,
    uint32_t b0, uint32_t b1)
{
    asm volatile(
        "mma.sync.aligned.m16n8k16.row.col.f32.bf16.bf16.f32 "
        "{%0,%1,%2,%3}, {%4,%5,%6,%7}, {%8,%9}, {%0,%1,%2,%3};"
        : "+f"(d[0]), "+f"(d[1]), "+f"(d[2]), "+f"(d[3])
        : "r"(a0), "r"(a1), "r"(a2), "r"(a3), "r"(b0), "r"(b1));
}

__device__ __forceinline__ void cp16(uint32_t dst_smem, const void* src)
{
    asm volatile("cp.async.ca.shared.global [%0], [%1], 16;"
                 :: "r"(dst_smem), "l"(src));
}
__device__ __forceinline__ void cp_commit()
{
    asm volatile("cp.async.commit_group;");
}
template<int N> __device__ __forceinline__ void cp_wait()
{
    asm volatile("cp.async.wait_group %0;" :: "n"(N));
}

// ---------------- split x and weights to bf16 hi/lo --------------------------
__global__ __launch_bounds__(256) void split5_k(
    const float* __restrict__ x,
    const float* __restrict__ Wq, const float* __restrict__ Wk,
    const float* __restrict__ Wv, const float* __restrict__ Wo)
{
    const int z = blockIdx.z;
    const float* src; __nv_bfloat16* hi; __nv_bfloat16* lo; size_t n;
    if (z == 0)      { src = x;  hi = g_xhi;         lo = g_xlo;         n = XSZ; }
    else if (z == 1) { src = Wq; hi = g_whi;         lo = g_wlo;         n = WSZ; }
    else if (z == 2) { src = Wk; hi = g_whi + WSZ;   lo = g_wlo + WSZ;   n = WSZ; }
    else if (z == 3) { src = Wv; hi = g_whi + 2*WSZ; lo = g_wlo + 2*WSZ; n = WSZ; }
    else             { src = Wo; hi = g_whi + 3*WSZ; lo = g_wlo + 3*WSZ; n = WSZ; }

    size_t i4 = (size_t)blockIdx.x * 256 + threadIdx.x;
    if (i4 * 4 >= n) return;
    float4 v = ((const float4*)src)[i4];
    float rx, ry, rz, rw;
    __nv_bfloat162 h0 = split_hi2(v.x, v.y, rx, ry);
    __nv_bfloat162 h1 = split_hi2(v.z, v.w, rz, rw);
    __nv_bfloat162 l0; l0.x = __float2bfloat16(rx); l0.y = __float2bfloat16(ry);
    __nv_bfloat162 l1; l1.x = __float2bfloat16(rz); l1.y = __float2bfloat16(rw);
    ((__nv_bfloat162*)hi)[i4*2    ] = h0;
    ((__nv_bfloat162*)hi)[i4*2 + 1] = h1;
    ((__nv_bfloat162*)lo)[i4*2    ] = l0;
    ((__nv_bfloat162*)lo)[i4*2 + 1] = l1;
}

// ---------------- 3xBF16 GEMM: m16n8k16, cp.async 2-stage --------------------
// BM=BN=128, BK=16, 256 threads (8 warps), warp tile 32x64.
// smem row = 8 uint32 (16 bf16) padded to pitch 12 (48B; conflict-free frags).
#define GP   12
#define GBUF (128*GP)          // uint32 per array per buffer (6 KB)
#define OFF_AH 0
#define OFF_AL (2*GBUF)
#define OFF_WH (4*GBUF)
#define OFF_WL (6*GBUF)
#define GSMEM  (8*GBUF*4)      // 49152 bytes

template<int ACT>
__device__ __forceinline__ void gemm_bf16x3(
    const __nv_bfloat16* __restrict__ Ahi, const __nv_bfloat16* __restrict__ Alo,
    const __nv_bfloat16* __restrict__ Whi, const __nv_bfloat16* __restrict__ Wlo,
    float* __restrict__ C, int M, int N, int K)
{
    extern __shared__ uint32_t smu[];
    const uint32_t sbase = (uint32_t)__cvta_generic_to_shared(smu);

    const int tid  = threadIdx.x;
    const int lane = tid & 31;
    const int wid  = tid >> 5;
    const int m0   = blockIdx.y * 128;
    const int n0   = blockIdx.x * 128;
    const int m0w  = (wid >> 1) * 32;
    const int n0w  = (wid & 1)  * 64;
    const int rr   = lane >> 2;
    const int qq   = lane & 3;

    float acc[2][8][4];
    #pragma unroll
    for (int i = 0; i < 2; ++i)
        #pragma unroll
        for (int j = 0; j < 8; ++j)
            #pragma unroll
            for (int r = 0; r < 4; ++r) acc[i][j][r] = 0.f;

    // each thread: one 16B segment (8 bf16) of one row, per array
    const int lrow = tid >> 1;        // 0..127
    const int lhalf = tid & 1;        // 0 or 1

    auto issue = [&](int b, int kt) {
        const int k0 = kt * 16 + lhalf * 8;
        const uint32_t soff = (uint32_t)((b*GBUF + lrow*GP) * 4 + lhalf * 16);
        const size_t ga = (size_t)(m0 + lrow) * K + k0;
        const size_t gw = (size_t)(n0 + lrow) * K + k0;
        cp16(sbase + OFF_AH*4 + soff, Ahi + ga);
        cp16(sbase + OFF_AL*4 + soff, Alo + ga);
        cp16(sbase + OFF_WH*4 + soff, Whi + gw);
        cp16(sbase + OFF_WL*4 + soff, Wlo + gw);
    };

    const int NT = K / 16;
    issue(0, 0);
    cp_commit();

    for (int kt = 0; kt < NT; ++kt) {
        const int cur = kt & 1;
        if (kt + 1 < NT) {
            issue(cur ^ 1, kt + 1);
            cp_commit();
            cp_wait<1>();
        } else {
            cp_wait<0>();
        }
        __syncthreads();

        const uint32_t* sAh = smu + OFF_AH + cur*GBUF;
        const uint32_t* sAl = smu + OFF_AL + cur*GBUF;
        const uint32_t* sWh = smu + OFF_WH + cur*GBUF;
        const uint32_t* sWl = smu + OFF_WL + cur*GBUF;

        uint32_t ah[2][4], al[2][4];
        #pragma unroll
        for (int i = 0; i < 2; ++i) {
            const int mb = m0w + i * 16;
            ah[i][0] = sAh[(mb+rr  )*GP + qq  ];
            ah[i][1] = sAh[(mb+rr+8)*GP + qq  ];
            ah[i][2] = sAh[(mb+rr  )*GP + qq+4];
            ah[i][3] = sAh[(mb+rr+8)*GP + qq+4];
            al[i][0] = sAl[(mb+rr  )*GP + qq  ];
            al[i][1] = sAl[(mb+rr+8)*GP + qq  ];
            al[i][2] = sAl[(mb+rr  )*GP + qq+4];
            al[i][3] = sAl[(mb+rr+8)*GP + qq+4];
        }
        #pragma unroll
        for (int j = 0; j < 8; ++j) {
            const int nb = n0w + j * 8 + rr;
            uint32_t bh0 = sWh[nb*GP + qq  ];
            uint32_t bh1 = sWh[nb*GP + qq+4];
            uint32_t bl0 = sWl[nb*GP + qq  ];
            uint32_t bl1 = sWl[nb*GP + qq+4];
            #pragma unroll
            for (int i = 0; i < 2; ++i) {
                mma_bf16(acc[i][j], ah[i][0], ah[i][1], ah[i][2], ah[i][3], bh0, bh1);
                mma_bf16(acc[i][j], ah[i][0], ah[i][1], ah[i][2], ah[i][3], bl0, bl1);
                mma_bf16(acc[i][j], al[i][0], al[i][1], al[i][2], al[i][3], bh0, bh1);
            }
        }
        __syncthreads();
    }

    #pragma unroll
    for (int i = 0; i < 2; ++i) {
        #pragma unroll
        for (int j = 0; j < 8; ++j) {
            const int row0 = m0 + m0w + i * 16 + rr;
            const int col  = n0 + n0w + j * 8 + qq * 2;
            float2 v0, v1;
            v0.x = acc[i][j][0]; v0.y = acc[i][j][1];
            v1.x = acc[i][j][2]; v1.y = acc[i][j][3];
            if (ACT == 1) {
                v0.x = siluf(v0.x); v0.y = siluf(v0.y);
                v1.x = siluf(v1.x); v1.y = siluf(v1.y);
            }
            *(float2*)&C[(size_t)row0       * N + col] = v0;
            *(float2*)&C[(size_t)(row0 + 8) * N + col] = v1;
        }
    }
}

__global__ __launch_bounds__(256, 2) void gemm_qkv(int M, int N, int K)
{
    const int z = blockIdx.z;
    gemm_bf16x3<1>(g_xhi, g_xlo, g_whi + (size_t)z*WSZ, g_wlo + (size_t)z*WSZ,
                   g_ptrs[z], M, N, K);
}

__global__ __launch_bounds__(256, 2) void gemm_out(float* __restrict__ C,
                                                   int M, int N, int K)
{
    gemm_bf16x3<0>(g_yhi, g_ylo, g_whi + 3*(size_t)WSZ, g_wlo + 3*(size_t)WSZ,
                   C, M, N, K);
}

// ---------------- beta = sigmoid(x @ Wbeta^T) --------------------------------
__global__ __launch_bounds__(128) void beta_gemv(
    const float* __restrict__ x, const float* __restrict__ Wb)
{
    const int row = blockIdx.x;
    __shared__ float xs[DM];
    const float4* xr = (const float4*)(x + (size_t)row * DM);
    float4* xs4 = (float4*)xs;
    xs4[threadIdx.x]       = xr[threadIdx.x];
    xs4[threadIdx.x + 128] = xr[threadIdx.x + 128];
    __syncthreads();

    const int j  = threadIdx.x >> 3;
    const int l8 = threadIdx.x & 7;
    const float* wr = Wb + (size_t)j * DM;
    float s = 0.f;
    for (int i = 0; i < DM/8; ++i) {
        int k = l8 + i*8;
        s += xs[k] * wr[k];
    }
    #pragma unroll
    for (int off = 4; off > 0; off >>= 1)
        s += __shfl_down_sync(0xffffffffu, s, off, 8);
    if (l8 == 0) g_beta[(size_t)row * NH + j] = sigmf(s);
}

// ---------------- per-head l2 normalize (in place) ---------------------------
__global__ __launch_bounds__(512) void l2norm_k()
{
    float* p = g_ptrs[blockIdx.y];   // 0 -> g_q, 1 -> g_k
    const int row  = blockIdx.x;
    const int w    = threadIdx.x >> 5;
    const int lane = threadIdx.x & 31;
    const size_t base = (size_t)row * DM + w * HD;
    float a = p[base + lane];
    float b = p[base + 32 + lane];
    float ss = a*a + b*b;
    #pragma unroll
    for (int off = 16; off > 0; off >>= 1)
        ss += __shfl_xor_sync(0xffffffffu, ss, off);
    float sc = 1.0f / (sqrtf(ss) + 1e-6f);
    p[base + lane]      = a * sc;
    p[base + 32 + lane] = b * sc;
}

// ---------------- small 64x64x64 smem FFMA micro-kernels ---------------------
__device__ __forceinline__ void gemm_rr(
    const float* __restrict__ A, const float* __restrict__ B,
    float (&acc)[4][4], int i0, int j0)
{
    #pragma unroll 4
    for (int x = 0; x < 64; ++x) {
        float a0 = A[(i0+0)*P65+x], a1 = A[(i0+1)*P65+x];
        float a2 = A[(i0+2)*P65+x], a3 = A[(i0+3)*P65+x];
        float b0 = B[(j0+0)*P65+x], b1 = B[(j0+1)*P65+x];
        float b2 = B[(j0+2)*P65+x], b3 = B[(j0+3)*P65+x];
        acc[0][0]+=a0*b0; acc[0][1]+=a0*b1; acc[0][2]+=a0*b2; acc[0][3]+=a0*b3;
        acc[1][0]+=a1*b0; acc[1][1]+=a1*b1; acc[1][2]+=a1*b2; acc[1][3]+=a1*b3;
        acc[2][0]+=a2*b0; acc[2][1]+=a2*b1; acc[2][2]+=a2*b2; acc[2][3]+=a2*b3;
        acc[3][0]+=a3*b0; acc[3][1]+=a3*b1; acc[3][2]+=a3*b2; acc[3][3]+=a3*b3;
    }
}

__device__ __forceinline__ void gemm_rc(
    const float* __restrict__ A, const float* __restrict__ B,
    float (&acc)[4][4], int i0, int j0)
{
    #pragma unroll 4
    for (int x = 0; x < 64; ++x) {
        float a0 = A[(i0+0)*P65+x], a1 = A[(i0+1)*P65+x];
        float a2 = A[(i0+2)*P65+x], a3 = A[(i0+3)*P65+x];
        float b0 = B[x*P65+j0+0], b1 = B[x*P65+j0+1];
        float b2 = B[x*P65+j0+2], b3 = B[x*P65+j0+3];
        acc[0][0]+=a0*b0; acc[0][1]+=a0*b1; acc[0][2]+=a0*b2; acc[0][3]+=a0*b3;
        acc[1][0]+=a1*b0; acc[1][1]+=a1*b1; acc[1][2]+=a1*b2; acc[1][3]+=a1*b3;
        acc[2][0]+=a2*b0; acc[2][1]+=a2*b1; acc[2][2]+=a2*b2; acc[2][3]+=a2*b3;
        acc[3][0]+=a3*b0; acc[3][1]+=a3*b1; acc[3][2]+=a3*b2; acc[3][3]+=a3*b3;
    }
}

__device__ __forceinline__ void gemm_cc(
    const float* __restrict__ A, const float* __restrict__ B,
    float (&acc)[4][4], int i0, int j0)
{
    #pragma unroll 4
    for (int x = 0; x < 64; ++x) {
        float a0 = A[x*P65+i0+0], a1 = A[x*P65+i0+1];
        float a2 = A[x*P65+i0+2], a3 = A[x*P65+i0+3];
        float b0 = B[x*P65+j0+0], b1 = B[x*P65+j0+1];
        float b2 = B[x*P65+j0+2], b3 = B[x*P65+j0+3];
        acc[0][0]+=a0*b0; acc[0][1]+=a0*b1; acc[0][2]+=a0*b2; acc[0][3]+=a0*b3;
        acc[1][0]+=a1*b0; acc[1][1]+=a1*b1; acc[1][2]+=a1*b2; acc[1][3]+=a1*b3;
        acc[2][0]+=a2*b0; acc[2][1]+=a2*b1; acc[2][2]+=a2*b2; acc[2][3]+=a2*b3;
        acc[3][0]+=a3*b0; acc[3][1]+=a3*b1; acc[3][2]+=a3*b2; acc[3][3]+=a3*b3;
    }
}

// ---------------- chunk pre-kernel: A = K K^T, KV = K V^T --------------------
__global__ __launch_bounds__(256) void chunk_pre_k()
{
    __shared__ float sK[64*P65];
    __shared__ float sV[64*P65];

    const int ci    = blockIdx.x;
    const int chain = ci >> 5;
    const int c     = ci & 31;
    const int b     = chain >> 4;
    const int n     = chain & 15;
    const int tid   = threadIdx.x;
    const int i0    = (tid >> 4) << 2;
    const int j0    = (tid & 15) << 2;
    const size_t rbase = (size_t)(b*SS + c*CHUNK);

    for (int idx = tid; idx < 4096; idx += 256) {
        int t = idx >> 6, h = idx & 63;
        size_t g = (rbase + t) * DM + n*HD + h;
        sK[t*P65+h] = g_k[g];
        sV[t*P65+h] = g_v[g];
    }
    __syncthreads();

    float acc[4][4];
    zero44(acc);
    gemm_rr(sK, sK, acc, i0, j0);
    #pragma unroll
    for (int i = 0; i < 4; ++i)
        #pragma unroll
        for (int j = 0; j < 4; ++j)
            g_A[(size_t)ci*4096 + (i0+i)*64 + j0+j] = acc[i][j];

    zero44(acc);
    gemm_rr(sK, sV, acc, i0, j0);
    #pragma unroll
    for (int i = 0; i < 4; ++i)
        #pragma unroll
        for (int j = 0; j < 4; ++j)
            g_KV[(size_t)ci*4096 + (i0+i)*64 + j0+j] = acc[i][j];
}

// ---------------- serial core (FFMA, proven): per chain, loop chunks ---------
#define CORE_SMEM ((7*64*P65 + 64) * 4)

__global__ __launch_bounds__(256) void delta_core_k()
{
    extern __shared__ float smc[];
    float* sM  = smc;
    float* sK  = sM  + 64*P65;
    float* sVU = sK  + 64*P65;
    float* sT1 = sVU + 64*P65;
    float* sR  = sT1 + 64*P65;
    float* sG  = sR  + 64*P65;
    float* sAm = sG  + 64*P65;
    float* sb  = sAm + 64*P65;

    const int chain = blockIdx.x;
    const int b     = chain >> 4;
    const int n     = chain & 15;
    const int tid   = threadIdx.x;
    const int i0    = (tid >> 4) << 2;
    const int j0    = (tid & 15) << 2;
    const int tp    = tid >> 2;
    const int sub   = tid & 3;

    for (int idx = tid; idx < 64*P65; idx += 256) sM[idx] = 0.f;
    __syncthreads();

    for (int c = 0; c < NCH; ++c) {
        const int ci = chain * NCH + c;
        const size_t rbase = (size_t)(b*SS + c*CHUNK);

        for (int idx = tid; idx < 4096; idx += 256) {
            int t = idx >> 6, h = idx & 63;
            size_t g = (rbase + t) * DM + n*HD + h;
            sK [t*P65+h] = g_k[g];
            sVU[t*P65+h] = g_v[g];
            sAm[t*P65+h] = g_A [(size_t)ci*4096 + idx];
            sR [t*P65+h] = g_KV[(size_t)ci*4096 + idx];
            sG [t*P65+h] = 0.f;
            g_M0[(size_t)ci*4096 + idx] = sM[t*P65+h];
        }
        if (tid < 64) sb[tid] = g_beta[(rbase + tid)*NH + n];
        __syncthreads();

        float acc[4][4];
        zero44(acc);
        gemm_rr(sK, sM, acc, i0, j0);
        #pragma unroll
        for (int i = 0; i < 4; ++i)
            #pragma unroll
            for (int j = 0; j < 4; ++j)
                sT1[(i0+i)*P65 + j0+j] = acc[i][j];
        __syncthreads();

        zero44(acc);
        gemm_rr(sK, sT1, acc, i0, j0);
        #pragma unroll
        for (int i = 0; i < 4; ++i)
            #pragma unroll
            for (int j = 0; j < 4; ++j)
                sR[(i0+i)*P65 + j0+j] -= acc[i][j];
        __syncthreads();

        for (int t = 0; t < 64; ++t) {
            float s = 0.f;
            for (int r = sub; r < t; r += 4)
                s += sG[t*P65+r] * sAm[tp*P65+r];
            s += __shfl_down_sync(0xffffffffu, s, 2, 4);
            s += __shfl_down_sync(0xffffffffu, s, 1, 4);
            if (sub == 0 && tp > t)
                sG[tp*P65+t] = sb[t] * (sR[tp*P65+t] - s);
            __syncthreads();
        }

        zero44(acc);
        gemm_rc(sG, sK, acc, i0, j0);
        #pragma unroll
        for (int i = 0; i < 4; ++i) {
            #pragma unroll
            for (int j = 0; j < 4; ++j) {
                const int t = i0+i, d = j0+j;
                float u = sb[t] * (sVU[t*P65+d] - sT1[t*P65+d] - acc[i][j]);
                sVU[t*P65+d] = u;
                g_U[(size_t)ci*4096 + t*64 + d] = u;
            }
        }
        __syncthreads();

        zero44(acc);
        gemm_cc(sK, sVU, acc, i0, j0);
        #pragma unroll
        for (int i = 0; i < 4; ++i)
            #pragma unroll
            for (int j = 0; j < 4; ++j)
                sM[(i0+i)*P65 + j0+j] += acc[i][j];
        __syncthreads();
    }
}

// ---------------- epilogue: Out = Q M0 + tril(QK^T,-1) U  --------------------
__global__ __launch_bounds__(256) void delta_out_k()
{
    extern __shared__ float smo[];
    float* sQ  = smo;
    float* sKQ = sQ  + 64*P65;
    float* sM0 = sKQ + 64*P65;
    float* sU  = sM0 + 64*P65;

    const int ci    = blockIdx.x;
    const int chain = ci >> 5;
    const int c     = ci & 31;
    const int b     = chain >> 4;
    const int n     = chain & 15;
    const int tid   = threadIdx.x;
    const int i0    = (tid >> 4) << 2;
    const int j0    = (tid & 15) << 2;
    const size_t rbase = (size_t)(b*SS + c*CHUNK);

    for (int idx = tid; idx < 4096; idx += 256) {
        int t = idx >> 6, h = idx & 63;
        size_t g = (rbase + t) * DM + n*HD + h;
        sQ [t*P65+h] = g_q[g];
        sKQ[t*P65+h] = g_k[g];
        sM0[t*P65+h] = g_M0[(size_t)ci*4096 + idx];
        sU [t*P65+h] = g_U [(size_t)ci*4096 + idx];
    }
    __syncthreads();

    float acc[4][4];
    zero44(acc);
    gemm_rr(sQ, sKQ, acc, i0, j0);
    __syncthreads();
    #pragma unroll
    for (int i = 0; i < 4; ++i)
        #pragma unroll
        for (int j = 0; j < 4; ++j)
            sKQ[(i0+i)*P65 + j0+j] = (i0+i) > (j0+j) ? acc[i][j] : 0.f;
    __syncthreads();

    zero44(acc);
    gemm_rc(sQ,  sM0, acc, i0, j0);
    gemm_rc(sKQ, sU,  acc, i0, j0);

    #pragma unroll
    for (int i = 0; i < 4; ++i)
        #pragma unroll
        for (int j = 0; j < 4; ++j)
            g_attn[(rbase + i0+i)*DM + n*HD + j0+j] = acc[i][j];
}

// ---------------- RMSNorm (fused bf16 split of y) ----------------------------
__global__ __launch_bounds__(256) void rmsnorm_k(const float* __restrict__ w)
{
    const float* x = g_attn;
    const int row = blockIdx.x;
    const float4* xr = (const float4*)(x + (size_t)row * DM);
    float4 xv = xr[threadIdx.x];
    float ss = xv.x*xv.x + xv.y*xv.y + xv.z*xv.z + xv.w*xv.w;

    __shared__ float red[8];
    #pragma unroll
    for (int off = 16; off > 0; off >>= 1)
        ss += __shfl_xor_sync(0xffffffffu, ss, off);
    if ((threadIdx.x & 31) == 0) red[threadIdx.x >> 5] = ss;
    __syncthreads();
    float total = 0.f;
    #pragma unroll
    for (int i = 0; i < 8; ++i) total += red[i];

    const float inv = rsqrtf(total * (1.0f/DM) + 1e-6f);
    const float4* wr = (const float4*)w;
    float4 wv = wr[threadIdx.x];
    float ox = xv.x * inv * wv.x;
    float oy = xv.y * inv * wv.y;
    float oz = xv.z * inv * wv.z;
    float ow = xv.w * inv * wv.w;

    float rx, ry, rz, rw;
    __nv_bfloat162 h0 = split_hi2(ox, oy, rx, ry);
    __nv_bfloat162 h1 = split_hi2(oz, ow, rz, rw);
    __nv_bfloat162 l0; l0.x = __float2bfloat16(rx); l0.y = __float2bfloat16(ry);
    __nv_bfloat162 l1; l1.x = __float2bfloat16(rz); l1.y = __float2bfloat16(rw);

    __nv_bfloat162* yh2 = (__nv_bfloat162*)(g_yhi + (size_t)row * DM);
    __nv_bfloat162* yl2 = (__nv_bfloat162*)(g_ylo + (size_t)row * DM);
    yh2[threadIdx.x*2    ] = h0;
    yh2[threadIdx.x*2 + 1] = h1;
    yl2[threadIdx.x*2    ] = l0;
    yl2[threadIdx.x*2 + 1] = l1;
}

// ---------------- launcher ---------------------------------------------------
extern "C" void kernel_launch(void* const* d_in, const int* in_sizes, int n_in,
                              void* d_out, int out_size)
{
    const float* x   = (const float*)d_in[0];
    const float* Wq  = (const float*)d_in[1];
    const float* Wk  = (const float*)d_in[2];
    const float* Wv  = (const float*)d_in[3];
    const float* Wo  = (const float*)d_in[4];
    const float* Wb  = (const float*)d_in[5];
    const float* rw  = (const float*)d_in[6];
    float* out = (float*)d_out;

    const int epi_smem  = (4*64*P65) * 4;
    cudaFuncSetAttribute(delta_core_k, cudaFuncAttributeMaxDynamicSharedMemorySize, CORE_SMEM);
    cudaFuncSetAttribute(delta_out_k,  cudaFuncAttributeMaxDynamicSharedMemorySize, epi_smem);
    cudaFuncSetAttribute(gemm_qkv, cudaFuncAttributeMaxDynamicSharedMemorySize, GSMEM);
    cudaFuncSetAttribute(gemm_out, cudaFuncAttributeMaxDynamicSharedMemorySize, GSMEM);

    init_ptrs_k<<<1, 1>>>();                             // 1

    dim3 gsplit(XSZ/4/256, 1, 5);
    split5_k<<<gsplit, 256>>>(x, Wq, Wk, Wv, Wo);        // 2

    beta_gemv<<<ROWS, 128>>>(x, Wb);                     // 3

    dim3 gqkv(DM/128, ROWS/128, 3);
    gemm_qkv<<<gqkv, 256, GSMEM>>>(ROWS, DM, DM);        // 4 <- profile slot

    dim3 gnorm(ROWS, 2);
    l2norm_k<<<gnorm, 512>>>();                          // 5

    chunk_pre_k<<<NCI, 256>>>();                         // 6
    delta_core_k<<<BB*NH, 256, CORE_SMEM>>>();           // 7
    delta_out_k<<<NCI, 256, epi_smem>>>();               // 8

    rmsnorm_k<<<ROWS, 256>>>(rw);                        // 9

    dim3 go(DM/128, ROWS/128);
    gemm_out<<<go, 256, GSMEM>>>(out, ROWS, DM, DM);     // 10
}

// round 12
// speedup vs baseline: 1.3798x; 1.0553x over previous
#include <cuda_runtime.h>
#include <cuda_bf16.h>
#include <math.h>
#include <stdint.h>

#define DM   1024
#define NH   16
#define HD   64
#define BB   4
#define SS   2048
#define ROWS (BB*SS)   // 8192
#define CHUNK 64
#define NCH  (SS/CHUNK)       // 32 chunks per chain
#define NCI  (BB*NH*NCH)      // 2048 chunk instances
#define P65  65

#define WSZ  (DM*DM)
#define XSZ  (ROWS*DM)

// ---------------- scratch (static device buffers; no allocation) ------------
__device__ float g_q[XSZ];
__device__ float g_k[XSZ];
__device__ float g_v[XSZ];
__device__ float g_beta[ROWS*NH];
__device__ float g_attn[XSZ];

// pre-split bf16 operands (x = hi + lo, both bf16)
__device__ __nv_bfloat16 g_xhi[XSZ];
__device__ __nv_bfloat16 g_xlo[XSZ];
__device__ __nv_bfloat16 g_yhi[XSZ];
__device__ __nv_bfloat16 g_ylo[XSZ];
__device__ __nv_bfloat16 g_whi[4*WSZ];   // Wq,Wk,Wv,Wo
__device__ __nv_bfloat16 g_wlo[4*WSZ];

// chunked delta-rule scratch
__device__ float g_A [NCI*4096];
__device__ float g_KV[NCI*4096];
__device__ float g_U [NCI*4096];
__device__ float g_M0[NCI*4096];

__device__ float* g_ptrs[4];

__global__ void init_ptrs_k()
{
    g_ptrs[0] = g_q;
    g_ptrs[1] = g_k;
    g_ptrs[2] = g_v;
    g_ptrs[3] = g_attn;
}

__device__ __forceinline__ float sigmf(float x){ return 1.0f/(1.0f+__expf(-x)); }
__device__ __forceinline__ float siluf(float x){ return x * sigmf(x); }

__device__ __forceinline__ void zero44(float (&acc)[4][4])
{
    #pragma unroll
    for (int i = 0; i < 4; ++i)
        #pragma unroll
        for (int j = 0; j < 4; ++j)
            acc[i][j] = 0.f;
}

// ---------------- bf16 split helpers -----------------------------------------
__device__ __forceinline__ __nv_bfloat162 split_hi2(float a, float b,
                                                    float& ra, float& rb)
{
    __nv_bfloat16 ha = __float2bfloat16(a);
    __nv_bfloat16 hb = __float2bfloat16(b);
    ra = a - __bfloat162float(ha);
    rb = b - __bfloat162float(hb);
    __nv_bfloat162 p; p.x = ha; p.y = hb; return p;
}

// ---------------- mma m16n8k16 bf16 ------------------------------------------
__device__ __forceinline__ void mma_bf16(float (&d)[4],
    uint32_t a0, uint32_t a1, uint32_t a2, uint32_t a3,
    uint32_t b0, uint32_t b1)
{
    asm volatile(
        "mma.sync.aligned.m16n8k16.row.col.f32.bf16.bf16.f32 "
        "{%0,%1,%2,%3}, {%4,%5,%6,%7}, {%8,%9}, {%0,%1,%2,%3};"
        : "+f"(d[0]), "+f"(d[1]), "+f"(d[2]), "+f"(d[3])
        : "r"(a0), "r"(a1), "r"(a2), "r"(a3), "r"(b0), "r"(b1));
}

__device__ __forceinline__ void ldm4(uint32_t& r0, uint32_t& r1,
                                     uint32_t& r2, uint32_t& r3, uint32_t addr)
{
    asm volatile("ldmatrix.sync.aligned.m8n8.x4.shared.b16 {%0,%1,%2,%3}, [%4];"
                 : "=r"(r0), "=r"(r1), "=r"(r2), "=r"(r3) : "r"(addr));
}

__device__ __forceinline__ void cp16(uint32_t dst_smem, const void* src)
{
    asm volatile("cp.async.ca.shared.global [%0], [%1], 16;"
                 :: "r"(dst_smem), "l"(src));
}
__device__ __forceinline__ void cp_commit()
{
    asm volatile("cp.async.commit_group;");
}
template<int N> __device__ __forceinline__ void cp_wait()
{
    asm volatile("cp.async.wait_group %0;" :: "n"(N));
}

// ---------------- split x and weights to bf16 hi/lo --------------------------
__global__ __launch_bounds__(256) void split5_k(
    const float* __restrict__ x,
    const float* __restrict__ Wq, const float* __restrict__ Wk,
    const float* __restrict__ Wv, const float* __restrict__ Wo)
{
    const int z = blockIdx.z;
    const float* src; __nv_bfloat16* hi; __nv_bfloat16* lo; size_t n;
    if (z == 0)      { src = x;  hi = g_xhi;         lo = g_xlo;         n = XSZ; }
    else if (z == 1) { src = Wq; hi = g_whi;         lo = g_wlo;         n = WSZ; }
    else if (z == 2) { src = Wk; hi = g_whi + WSZ;   lo = g_wlo + WSZ;   n = WSZ; }
    else if (z == 3) { src = Wv; hi = g_whi + 2*WSZ; lo = g_wlo + 2*WSZ; n = WSZ; }
    else             { src = Wo; hi = g_whi + 3*WSZ; lo = g_wlo + 3*WSZ; n = WSZ; }

    size_t i4 = (size_t)blockIdx.x * 256 + threadIdx.x;
    if (i4 * 4 >= n) return;
    float4 v = ((const float4*)src)[i4];
    float rx, ry, rz, rw;
    __nv_bfloat162 h0 = split_hi2(v.x, v.y, rx, ry);
    __nv_bfloat162 h1 = split_hi2(v.z, v.w, rz, rw);
    __nv_bfloat162 l0; l0.x = __float2bfloat16(rx); l0.y = __float2bfloat16(ry);
    __nv_bfloat162 l1; l1.x = __float2bfloat16(rz); l1.y = __float2bfloat16(rw);
    ((__nv_bfloat162*)hi)[i4*2    ] = h0;
    ((__nv_bfloat162*)hi)[i4*2 + 1] = h1;
    ((__nv_bfloat162*)lo)[i4*2    ] = l0;
    ((__nv_bfloat162*)lo)[i4*2 + 1] = l1;
}

// ---------------- 3xBF16 GEMM: ldmatrix frags, cp.async 2-stage --------------
// BM=BN=128, BK=16, 256 threads (8 warps), warp tile 32x64.
// smem row = 8 uint32 (16 bf16) padded to pitch 12 (48B; conflict-free).
#define GP   12
#define GBUF (128*GP)          // uint32 per array per buffer
#define OFF_AH 0
#define OFF_AL (2*GBUF)
#define OFF_WH (4*GBUF)
#define OFF_WL (6*GBUF)
#define GSMEM  (8*GBUF*4)      // 49152 bytes

// ACT: 0 = none (output proj), 1 = SiLU (+ optional per-head l2norm via flag)
template<int ACT>
__device__ __forceinline__ void gemm_bf16x3(
    const __nv_bfloat16* __restrict__ Ahi, const __nv_bfloat16* __restrict__ Alo,
    const __nv_bfloat16* __restrict__ Whi, const __nv_bfloat16* __restrict__ Wlo,
    float* __restrict__ C, int M, int N, int K, int do_norm)
{
    extern __shared__ uint32_t smu[];
    const uint32_t sbase = (uint32_t)__cvta_generic_to_shared(smu);

    const int tid  = threadIdx.x;
    const int lane = tid & 31;
    const int wid  = tid >> 5;
    const int m0   = blockIdx.y * 128;
    const int n0   = blockIdx.x * 128;
    const int m0w  = (wid >> 1) * 32;
    const int n0w  = (wid & 1)  * 64;
    const int rr   = lane >> 2;
    const int qq   = lane & 3;

    // ldmatrix per-lane source coordinates
    const int aRow = lane & 15;               // row within m16 tile
    const int aKw  = (lane >> 4) * 4;         // k-half word offset
    const int bRow = ((lane >> 4) * 8) + (lane & 7);   // row within n16 pair
    const int bKw  = ((lane >> 3) & 1) * 4;

    float acc[2][8][4];
    #pragma unroll
    for (int i = 0; i < 2; ++i)
        #pragma unroll
        for (int j = 0; j < 8; ++j)
            #pragma unroll
            for (int r = 0; r < 4; ++r) acc[i][j][r] = 0.f;

    const int lrow  = tid >> 1;
    const int lhalf = tid & 1;

    auto issue = [&](int b, int kt) {
        const int k0 = kt * 16 + lhalf * 8;
        const uint32_t soff = (uint32_t)((b*GBUF + lrow*GP) * 4 + lhalf * 16);
        const size_t ga = (size_t)(m0 + lrow) * K + k0;
        const size_t gw = (size_t)(n0 + lrow) * K + k0;
        cp16(sbase + OFF_AH*4 + soff, Ahi + ga);
        cp16(sbase + OFF_AL*4 + soff, Alo + ga);
        cp16(sbase + OFF_WH*4 + soff, Whi + gw);
        cp16(sbase + OFF_WL*4 + soff, Wlo + gw);
    };

    const int NT = K / 16;
    issue(0, 0);
    cp_commit();

    for (int kt = 0; kt < NT; ++kt) {
        const int cur = kt & 1;
        if (kt + 1 < NT) {
            issue(cur ^ 1, kt + 1);
            cp_commit();
            cp_wait<1>();
        } else {
            cp_wait<0>();
        }
        __syncthreads();

        const uint32_t baseAH = sbase + (OFF_AH + cur*GBUF) * 4;
        const uint32_t baseAL = sbase + (OFF_AL + cur*GBUF) * 4;
        const uint32_t baseWH = sbase + (OFF_WH + cur*GBUF) * 4;
        const uint32_t baseWL = sbase + (OFF_WL + cur*GBUF) * 4;

        uint32_t ah[2][4], al[2][4];
        #pragma unroll
        for (int i = 0; i < 2; ++i) {
            const uint32_t wo = (uint32_t)(((m0w + i*16 + aRow)*GP + aKw) * 4);
            ldm4(ah[i][0], ah[i][1], ah[i][2], ah[i][3], baseAH + wo);
            ldm4(al[i][0], al[i][1], al[i][2], al[i][3], baseAL + wo);
        }
        #pragma unroll
        for (int jp = 0; jp < 4; ++jp) {
            const uint32_t wo = (uint32_t)(((n0w + jp*16 + bRow)*GP + bKw) * 4);
            uint32_t bh0, bh1, bh2, bh3, bl0, bl1, bl2, bl3;
            ldm4(bh0, bh1, bh2, bh3, baseWH + wo);
            ldm4(bl0, bl1, bl2, bl3, baseWL + wo);
            #pragma unroll
            for (int i = 0; i < 2; ++i) {
                mma_bf16(acc[i][2*jp  ], ah[i][0], ah[i][1], ah[i][2], ah[i][3], bh0, bh1);
                mma_bf16(acc[i][2*jp  ], ah[i][0], ah[i][1], ah[i][2], ah[i][3], bl0, bl1);
                mma_bf16(acc[i][2*jp  ], al[i][0], al[i][1], al[i][2], al[i][3], bh0, bh1);
                mma_bf16(acc[i][2*jp+1], ah[i][0], ah[i][1], ah[i][2], ah[i][3], bh2, bh3);
                mma_bf16(acc[i][2*jp+1], ah[i][0], ah[i][1], ah[i][2], ah[i][3], bl2, bl3);
                mma_bf16(acc[i][2*jp+1], al[i][0], al[i][1], al[i][2], al[i][3], bh2, bh3);
            }
        }
        __syncthreads();
    }

    if (ACT == 1) {
        // SiLU
        #pragma unroll
        for (int i = 0; i < 2; ++i)
            #pragma unroll
            for (int j = 0; j < 8; ++j)
                #pragma unroll
                for (int r = 0; r < 4; ++r)
                    acc[i][j][r] = siluf(acc[i][j][r]);

        if (do_norm) {
            // per-head l2 normalize: warp spans exactly one 64-col head
            float ss[2][2] = {{0.f, 0.f}, {0.f, 0.f}};
            #pragma unroll
            for (int i = 0; i < 2; ++i)
                #pragma unroll
                for (int j = 0; j < 8; ++j) {
                    ss[i][0] += acc[i][j][0]*acc[i][j][0] + acc[i][j][1]*acc[i][j][1];
                    ss[i][1] += acc[i][j][2]*acc[i][j][2] + acc[i][j][3]*acc[i][j][3];
                }
            #pragma unroll
            for (int i = 0; i < 2; ++i)
                #pragma unroll
                for (int s = 0; s < 2; ++s) {
                    float v = ss[i][s];
                    v += __shfl_xor_sync(0xffffffffu, v, 1, 4);
                    v += __shfl_xor_sync(0xffffffffu, v, 2, 4);
                    ss[i][s] = 1.0f / (sqrtf(v) + 1e-6f);
                }
            #pragma unroll
            for (int i = 0; i < 2; ++i)
                #pragma unroll
                for (int j = 0; j < 8; ++j) {
                    acc[i][j][0] *= ss[i][0]; acc[i][j][1] *= ss[i][0];
                    acc[i][j][2] *= ss[i][1]; acc[i][j][3] *= ss[i][1];
                }
        }
    }

    #pragma unroll
    for (int i = 0; i < 2; ++i) {
        #pragma unroll
        for (int j = 0; j < 8; ++j) {
            const int row0 = m0 + m0w + i * 16 + rr;
            const int col  = n0 + n0w + j * 8 + qq * 2;
            float2 v0, v1;
            v0.x = acc[i][j][0]; v0.y = acc[i][j][1];
            v1.x = acc[i][j][2]; v1.y = acc[i][j][3];
            *(float2*)&C[(size_t)row0       * N + col] = v0;
            *(float2*)&C[(size_t)(row0 + 8) * N + col] = v1;
        }
    }
}

__global__ __launch_bounds__(256, 2) void gemm_qkv(int M, int N, int K)
{
    const int z = blockIdx.z;
    gemm_bf16x3<1>(g_xhi, g_xlo, g_whi + (size_t)z*WSZ, g_wlo + (size_t)z*WSZ,
                   g_ptrs[z], M, N, K, z < 2 ? 1 : 0);
}

__global__ __launch_bounds__(256, 2) void gemm_out(float* __restrict__ C,
                                                   int M, int N, int K)
{
    gemm_bf16x3<0>(g_yhi, g_ylo, g_whi + 3*(size_t)WSZ, g_wlo + 3*(size_t)WSZ,
                   C, M, N, K, 0);
}

// ---------------- beta = sigmoid(x @ Wbeta^T) --------------------------------
__global__ __launch_bounds__(128) void beta_gemv(
    const float* __restrict__ x, const float* __restrict__ Wb)
{
    const int row = blockIdx.x;
    __shared__ float xs[DM];
    const float4* xr = (const float4*)(x + (size_t)row * DM);
    float4* xs4 = (float4*)xs;
    xs4[threadIdx.x]       = xr[threadIdx.x];
    xs4[threadIdx.x + 128] = xr[threadIdx.x + 128];
    __syncthreads();

    const int j  = threadIdx.x >> 3;
    const int l8 = threadIdx.x & 7;
    const float* wr = Wb + (size_t)j * DM;
    float s = 0.f;
    for (int i = 0; i < DM/8; ++i) {
        int k = l8 + i*8;
        s += xs[k] * wr[k];
    }
    #pragma unroll
    for (int off = 4; off > 0; off >>= 1)
        s += __shfl_down_sync(0xffffffffu, s, off, 8);
    if (l8 == 0) g_beta[(size_t)row * NH + j] = sigmf(s);
}

// ---------------- small 64x64x64 smem FFMA micro-kernels ---------------------
__device__ __forceinline__ void gemm_rr(
    const float* __restrict__ A, const float* __restrict__ B,
    float (&acc)[4][4], int i0, int j0)
{
    #pragma unroll 4
    for (int x = 0; x < 64; ++x) {
        float a0 = A[(i0+0)*P65+x], a1 = A[(i0+1)*P65+x];
        float a2 = A[(i0+2)*P65+x], a3 = A[(i0+3)*P65+x];
        float b0 = B[(j0+0)*P65+x], b1 = B[(j0+1)*P65+x];
        float b2 = B[(j0+2)*P65+x], b3 = B[(j0+3)*P65+x];
        acc[0][0]+=a0*b0; acc[0][1]+=a0*b1; acc[0][2]+=a0*b2; acc[0][3]+=a0*b3;
        acc[1][0]+=a1*b0; acc[1][1]+=a1*b1; acc[1][2]+=a1*b2; acc[1][3]+=a1*b3;
        acc[2][0]+=a2*b0; acc[2][1]+=a2*b1; acc[2][2]+=a2*b2; acc[2][3]+=a2*b3;
        acc[3][0]+=a3*b0; acc[3][1]+=a3*b1; acc[3][2]+=a3*b2; acc[3][3]+=a3*b3;
    }
}

__device__ __forceinline__ void gemm_rc(
    const float* __restrict__ A, const float* __restrict__ B,
    float (&acc)[4][4], int i0, int j0)
{
    #pragma unroll 4
    for (int x = 0; x < 64; ++x) {
        float a0 = A[(i0+0)*P65+x], a1 = A[(i0+1)*P65+x];
        float a2 = A[(i0+2)*P65+x], a3 = A[(i0+3)*P65+x];
        float b0 = B[x*P65+j0+0], b1 = B[x*P65+j0+1];
        float b2 = B[x*P65+j0+2], b3 = B[x*P65+j0+3];
        acc[0][0]+=a0*b0; acc[0][1]+=a0*b1; acc[0][2]+=a0*b2; acc[0][3]+=a0*b3;
        acc[1][0]+=a1*b0; acc[1][1]+=a1*b1; acc[1][2]+=a1*b2; acc[1][3]+=a1*b3;
        acc[2][0]+=a2*b0; acc[2][1]+=a2*b1; acc[2][2]+=a2*b2; acc[2][3]+=a2*b3;
        acc[3][0]+=a3*b0; acc[3][1]+=a3*b1; acc[3][2]+=a3*b2; acc[3][3]+=a3*b3;
    }
}

__device__ __forceinline__ void gemm_cc(
    const float* __restrict__ A, const float* __restrict__ B,
    float (&acc)[4][4], int i0, int j0)
{
    #pragma unroll 4
    for (int x = 0; x < 64; ++x) {
        float a0 = A[x*P65+i0+0], a1 = A[x*P65+i0+1];
        float a2 = A[x*P65+i0+2], a3 = A[x*P65+i0+3];
        float b0 = B[x*P65+j0+0], b1 = B[x*P65+j0+1];
        float b2 = B[x*P65+j0+2], b3 = B[x*P65+j0+3];
        acc[0][0]+=a0*b0; acc[0][1]+=a0*b1; acc[0][2]+=a0*b2; acc[0][3]+=a0*b3;
        acc[1][0]+=a1*b0; acc[1][1]+=a1*b1; acc[1][2]+=a1*b2; acc[1][3]+=a1*b3;
        acc[2][0]+=a2*b0; acc[2][1]+=a2*b1; acc[2][2]+=a2*b2; acc[2][3]+=a2*b3;
        acc[3][0]+=a3*b0; acc[3][1]+=a3*b1; acc[3][2]+=a3*b2; acc[3][3]+=a3*b3;
    }
}

// ---------------- chunk pre-kernel: A = K K^T, KV = K V^T --------------------
__global__ __launch_bounds__(256) void chunk_pre_k()
{
    __shared__ float sK[64*P65];
    __shared__ float sV[64*P65];

    const int ci    = blockIdx.x;
    const int chain = ci >> 5;
    const int c     = ci & 31;
    const int b     = chain >> 4;
    const int n     = chain & 15;
    const int tid   = threadIdx.x;
    const int i0    = (tid >> 4) << 2;
    const int j0    = (tid & 15) << 2;
    const size_t rbase = (size_t)(b*SS + c*CHUNK);

    for (int idx = tid; idx < 4096; idx += 256) {
        int t = idx >> 6, h = idx & 63;
        size_t g = (rbase + t) * DM + n*HD + h;
        sK[t*P65+h] = g_k[g];
        sV[t*P65+h] = g_v[g];
    }
    __syncthreads();

    float acc[4][4];
    zero44(acc);
    gemm_rr(sK, sK, acc, i0, j0);
    #pragma unroll
    for (int i = 0; i < 4; ++i)
        #pragma unroll
        for (int j = 0; j < 4; ++j)
            g_A[(size_t)ci*4096 + (i0+i)*64 + j0+j] = acc[i][j];

    zero44(acc);
    gemm_rr(sK, sV, acc, i0, j0);
    #pragma unroll
    for (int i = 0; i < 4; ++i)
        #pragma unroll
        for (int j = 0; j < 4; ++j)
            g_KV[(size_t)ci*4096 + (i0+i)*64 + j0+j] = acc[i][j];
}

// ---------------- serial core (FFMA, proven): per chain, loop chunks ---------
#define CORE_SMEM ((7*64*P65 + 64) * 4)

__global__ __launch_bounds__(256) void delta_core_k()
{
    extern __shared__ float smc[];
    float* sM  = smc;
    float* sK  = sM  + 64*P65;
    float* sVU = sK  + 64*P65;
    float* sT1 = sVU + 64*P65;
    float* sR  = sT1 + 64*P65;
    float* sG  = sR  + 64*P65;
    float* sAm = sG  + 64*P65;
    float* sb  = sAm + 64*P65;

    const int chain = blockIdx.x;
    const int b     = chain >> 4;
    const int n     = chain & 15;
    const int tid   = threadIdx.x;
    const int i0    = (tid >> 4) << 2;
    const int j0    = (tid & 15) << 2;
    const int tp    = tid >> 2;
    const int sub   = tid & 3;

    for (int idx = tid; idx < 64*P65; idx += 256) sM[idx] = 0.f;
    __syncthreads();

    for (int c = 0; c < NCH; ++c) {
        const int ci = chain * NCH + c;
        const size_t rbase = (size_t)(b*SS + c*CHUNK);

        for (int idx = tid; idx < 4096; idx += 256) {
            int t = idx >> 6, h = idx & 63;
            size_t g = (rbase + t) * DM + n*HD + h;
            sK [t*P65+h] = g_k[g];
            sVU[t*P65+h] = g_v[g];
            sAm[t*P65+h] = g_A [(size_t)ci*4096 + idx];
            sR [t*P65+h] = g_KV[(size_t)ci*4096 + idx];
            sG [t*P65+h] = 0.f;
            g_M0[(size_t)ci*4096 + idx] = sM[t*P65+h];
        }
        if (tid < 64) sb[tid] = g_beta[(rbase + tid)*NH + n];
        __syncthreads();

        float acc[4][4];
        zero44(acc);
        gemm_rr(sK, sM, acc, i0, j0);
        #pragma unroll
        for (int i = 0; i < 4; ++i)
            #pragma unroll
            for (int j = 0; j < 4; ++j)
                sT1[(i0+i)*P65 + j0+j] = acc[i][j];
        __syncthreads();

        zero44(acc);
        gemm_rr(sK, sT1, acc, i0, j0);
        #pragma unroll
        for (int i = 0; i < 4; ++i)
            #pragma unroll
            for (int j = 0; j < 4; ++j)
                sR[(i0+i)*P65 + j0+j] -= acc[i][j];
        __syncthreads();

        for (int t = 0; t < 64; ++t) {
            float s = 0.f;
            for (int r = sub; r < t; r += 4)
                s += sG[t*P65+r] * sAm[tp*P65+r];
            s += __shfl_down_sync(0xffffffffu, s, 2, 4);
            s += __shfl_down_sync(0xffffffffu, s, 1, 4);
            if (sub == 0 && tp > t)
                sG[tp*P65+t] = sb[t] * (sR[tp*P65+t] - s);
            __syncthreads();
        }

        zero44(acc);
        gemm_rc(sG, sK, acc, i0, j0);
        #pragma unroll
        for (int i = 0; i < 4; ++i) {
            #pragma unroll
            for (int j = 0; j < 4; ++j) {
                const int t = i0+i, d = j0+j;
                float u = sb[t] * (sVU[t*P65+d] - sT1[t*P65+d] - acc[i][j]);
                sVU[t*P65+d] = u;
                g_U[(size_t)ci*4096 + t*64 + d] = u;
            }
        }
        __syncthreads();

        zero44(acc);
        gemm_cc(sK, sVU, acc, i0, j0);
        #pragma unroll
        for (int i = 0; i < 4; ++i)
            #pragma unroll
            for (int j = 0; j < 4; ++j)
                sM[(i0+i)*P65 + j0+j] += acc[i][j];
        __syncthreads();
    }
}

// ---------------- epilogue: Out = Q M0 + tril(QK^T,-1) U  --------------------
__global__ __launch_bounds__(256) void delta_out_k()
{
    extern __shared__ float smo[];
    float* sQ  = smo;
    float* sKQ = sQ  + 64*P65;
    float* sM0 = sKQ + 64*P65;
    float* sU  = sM0 + 64*P65;

    const int ci    = blockIdx.x;
    const int chain = ci >> 5;
    const int c     = ci & 31;
    const int b     = chain >> 4;
    const int n     = chain & 15;
    const int tid   = threadIdx.x;
    const int i0    = (tid >> 4) << 2;
    const int j0    = (tid & 15) << 2;
    const size_t rbase = (size_t)(b*SS + c*CHUNK);

    for (int idx = tid; idx < 4096; idx += 256) {
        int t = idx >> 6, h = idx & 63;
        size_t g = (rbase + t) * DM + n*HD + h;
        sQ [t*P65+h] = g_q[g];
        sKQ[t*P65+h] = g_k[g];
        sM0[t*P65+h] = g_M0[(size_t)ci*4096 + idx];
        sU [t*P65+h] = g_U [(size_t)ci*4096 + idx];
    }
    __syncthreads();

    float acc[4][4];
    zero44(acc);
    gemm_rr(sQ, sKQ, acc, i0, j0);
    __syncthreads();
    #pragma unroll
    for (int i = 0; i < 4; ++i)
        #pragma unroll
        for (int j = 0; j < 4; ++j)
            sKQ[(i0+i)*P65 + j0+j] = (i0+i) > (j0+j) ? acc[i][j] : 0.f;
    __syncthreads();

    zero44(acc);
    gemm_rc(sQ,  sM0, acc, i0, j0);
    gemm_rc(sKQ, sU,  acc, i0, j0);

    #pragma unroll
    for (int i = 0; i < 4; ++i)
        #pragma unroll
        for (int j = 0; j < 4; ++j)
            g_attn[(rbase + i0+i)*DM + n*HD + j0+j] = acc[i][j];
}

// ---------------- RMSNorm (fused bf16 split of y) ----------------------------
__global__ __launch_bounds__(256) void rmsnorm_k(const float* __restrict__ w)
{
    const float* x = g_attn;
    const int row = blockIdx.x;
    const float4* xr = (const float4*)(x + (size_t)row * DM);
    float4 xv = xr[threadIdx.x];
    float ss = xv.x*xv.x + xv.y*xv.y + xv.z*xv.z + xv.w*xv.w;

    __shared__ float red[8];
    #pragma unroll
    for (int off = 16; off > 0; off >>= 1)
        ss += __shfl_xor_sync(0xffffffffu, ss, off);
    if ((threadIdx.x & 31) == 0) red[threadIdx.x >> 5] = ss;
    __syncthreads();
    float total = 0.f;
    #pragma unroll
    for (int i = 0; i < 8; ++i) total += red[i];

    const float inv = rsqrtf(total * (1.0f/DM) + 1e-6f);
    const float4* wr = (const float4*)w;
    float4 wv = wr[threadIdx.x];
    float ox = xv.x * inv * wv.x;
    float oy = xv.y * inv * wv.y;
    float oz = xv.z * inv * wv.z;
    float ow = xv.w * inv * wv.w;

    float rx, ry, rz, rw;
    __nv_bfloat162 h0 = split_hi2(ox, oy, rx, ry);
    __nv_bfloat162 h1 = split_hi2(oz, ow, rz, rw);
    __nv_bfloat162 l0; l0.x = __float2bfloat16(rx); l0.y = __float2bfloat16(ry);
    __nv_bfloat162 l1; l1.x = __float2bfloat16(rz); l1.y = __float2bfloat16(rw);

    __nv_bfloat162* yh2 = (__nv_bfloat162*)(g_yhi + (size_t)row * DM);
    __nv_bfloat162* yl2 = (__nv_bfloat162*)(g_ylo + (size_t)row * DM);
    yh2[threadIdx.x*2    ] = h0;
    yh2[threadIdx.x*2 + 1] = h1;
    yl2[threadIdx.x*2    ] = l0;
    yl2[threadIdx.x*2 + 1] = l1;
}

// ---------------- launcher ---------------------------------------------------
extern "C" void kernel_launch(void* const* d_in, const int* in_sizes, int n_in,
                              void* d_out, int out_size)
{
    const float* x   = (const float*)d_in[0];
    const float* Wq  = (const float*)d_in[1];
    const float* Wk  = (const float*)d_in[2];
    const float* Wv  = (const float*)d_in[3];
    const float* Wo  = (const float*)d_in[4];
    const float* Wb  = (const float*)d_in[5];
    const float* rw  = (const float*)d_in[6];
    float* out = (float*)d_out;

    const int epi_smem  = (4*64*P65) * 4;
    cudaFuncSetAttribute(delta_core_k, cudaFuncAttributeMaxDynamicSharedMemorySize, CORE_SMEM);
    cudaFuncSetAttribute(delta_out_k,  cudaFuncAttributeMaxDynamicSharedMemorySize, epi_smem);
    cudaFuncSetAttribute(gemm_qkv, cudaFuncAttributeMaxDynamicSharedMemorySize, GSMEM);
    cudaFuncSetAttribute(gemm_out, cudaFuncAttributeMaxDynamicSharedMemorySize, GSMEM);

    init_ptrs_k<<<1, 1>>>();                             // 1

    dim3 gsplit(XSZ/4/256, 1, 5);
    split5_k<<<gsplit, 256>>>(x, Wq, Wk, Wv, Wo);        // 2

    beta_gemv<<<ROWS, 128>>>(x, Wb);                     // 3

    dim3 gqkv(DM/128, ROWS/128, 3);
    gemm_qkv<<<gqkv, 256, GSMEM>>>(ROWS, DM, DM);        // 4 <- profile slot

    chunk_pre_k<<<NCI, 256>>>();                         // 5
    delta_core_k<<<BB*NH, 256, CORE_SMEM>>>();           // 6
    delta_out_k<<<NCI, 256, epi_smem>>>();               // 7

    rmsnorm_k<<<ROWS, 256>>>(rw);                        // 8

    dim3 go(DM/128, ROWS/128);
    gemm_out<<<go, 256, GSMEM>>>(out, ROWS, DM, DM);     // 9
}